// round 1
// baseline (speedup 1.0000x reference)
#include <cuda_runtime.h>
#include <math.h>

// Problem constants
#define RPB 128      // rows per block
#define TPB 256      // threads per block
#define WSTRIDE 132  // padded row stride (floats) for sW2 / sZ1: 132*4B = 528B, 16B aligned, 4-bank step

// Shared layout (floats):
//  sW2  [128][132]  = 16896
//  sZ1  [128][132]  = 16896
//  sW1  [128*12]    = 1536
//  sW3  [6*128]     = 768
//  sWih [12*21]     = 252
//  sWhh [12*12]     = 144
//  sH1  [128][12]   = 1536
//  sSE  [128][18]   = 2304   (Rinv 9, pinv 3, vI 6)
//  sDV  [128][6]    = 768
//  sS   [128][18]   = 2304
//  sA   [128][6]    = 768
//  sH0  [128][12]   = 1536
#define SMEM_FLOATS (16896*2 + 1536 + 768 + 252 + 144 + 1536 + 2304 + 768 + 2304 + 768 + 1536)
#define SMEM_BYTES (SMEM_FLOATS * 4)

__device__ __forceinline__ float lrelu(float z) { return z >= 0.0f ? z : 0.1f * z; }

__global__ __launch_bounds__(TPB, 1)
void auv_step_kernel(const float* __restrict__ s,
                     const float* __restrict__ a,
                     const float* __restrict__ h0,
                     const float* __restrict__ Wih,
                     const float* __restrict__ Whh,
                     const float* __restrict__ W1,
                     const float* __restrict__ W2,
                     const float* __restrict__ W3,
                     float* __restrict__ out,
                     int Krows)
{
    extern __shared__ float sm[];
    float* sW2  = sm;                    // [128][132]
    float* sZ1  = sW2  + 128 * WSTRIDE;  // [128][132]
    float* sW1  = sZ1  + 128 * WSTRIDE;  // [128][12]
    float* sW3  = sW1  + 1536;           // [6][128]
    float* sWih = sW3  + 768;            // [12][21]
    float* sWhh = sWih + 252;            // [12][12]
    float* sH1  = sWhh + 144;            // [128][12]
    float* sSE  = sH1  + 1536;           // [128][18]
    float* sDV  = sSE  + 2304;           // [128][6]
    float* sS   = sDV  + 768;            // [128][18]
    float* sA   = sS   + 2304;           // [128][6]
    float* sH0  = sA   + 768;            // [128][12]

    const int tid = threadIdx.x;
    const long long rowBase = (long long)blockIdx.x * RPB;
    const long long Kll = (long long)Krows;

    // ---- cooperative staging ----
    for (int i = tid; i < 128 * 128; i += TPB)
        sW2[(i >> 7) * WSTRIDE + (i & 127)] = W2[i];
    for (int i = tid; i < 1536; i += TPB) sW1[i] = W1[i];
    for (int i = tid; i < 768;  i += TPB) sW3[i] = W3[i];
    if (tid < 252) sWih[tid] = Wih[tid];
    if (tid < 144) sWhh[tid] = Whh[tid];
    for (int i = tid; i < RPB * 18; i += TPB) sS[i]  = s [rowBase * 18 + i];
    for (int i = tid; i < RPB * 6;  i += TPB) sA[i]  = a [rowBase * 6  + i];
    for (int i = tid; i < RPB * 12; i += TPB) sH0[i] = h0[rowBase * 12 + i];
    __syncthreads();

    // ---- phase 1: RNN cell (h1) + SE(3) per-row precompute ----
    if (tid < RPB) {
        const int r = tid;
        const long long g = rowBase + r;
        const float* Sr  = sS  + r * 18;
        const float* Ar  = sA  + r * 6;
        const float* H0r = sH0 + r * 12;

        float x[21];
        #pragma unroll
        for (int i = 0; i < 15; i++) x[i] = Sr[3 + i];
        #pragma unroll
        for (int i = 0; i < 6; i++) x[15 + i] = Ar[i];

        #pragma unroll
        for (int j = 0; j < 12; j++) {
            float acc = 0.0f;
            #pragma unroll
            for (int i = 0; i < 21; i++) acc += x[i] * sWih[j * 21 + i];
            #pragma unroll
            for (int i = 0; i < 12; i++) acc += H0r[i] * sWhh[j * 12 + i];
            float hv = tanhf(acc);
            sH1[r * 12 + j] = hv;
            out[Kll * 18 + g * 12 + j] = hv;   // hN output
        }

        // SE(3)
        const float p0 = Sr[0], p1 = Sr[1], p2 = Sr[2];
        float R[9];
        #pragma unroll
        for (int i = 0; i < 9; i++) R[i] = Sr[3 + i];
        float v[6];
        #pragma unroll
        for (int i = 0; i < 6; i++) v[i] = Sr[12 + i];

        const float DT = 0.1f;
        const float rho0 = v[0] * DT, rho1 = v[1] * DT, rho2 = v[2] * DT;
        const float px = v[3] * DT, py = v[4] * DT, pz = v[5] * DT;
        const float th2 = px * px + py * py + pz * pz;
        const bool small = th2 < 1e-8f;
        const float th2s = small ? 1.0f : th2;
        const float th = sqrtf(th2s);
        const float sth = sinf(th), cth = cosf(th);
        const float A = small ? (1.0f - th2 * (1.0f / 6.0f))  : (sth / th);
        const float B = small ? (0.5f - th2 * (1.0f / 24.0f)) : ((1.0f - cth) / th2s);
        const float C = small ? (1.0f / 6.0f - th2 * (1.0f / 120.0f)) : ((th - sth) / (th2s * th));

        const float S[9]  = {0.0f, -pz, py,  pz, 0.0f, -px,  -py, px, 0.0f};
        float S2[9];
        S2[0] = -(py * py + pz * pz); S2[1] = px * py;              S2[2] = px * pz;
        S2[3] = px * py;              S2[4] = -(px * px + pz * pz); S2[5] = py * pz;
        S2[6] = px * pz;              S2[7] = py * pz;              S2[8] = -(px * px + py * py);

        float Re[9], Vm[9];
        #pragma unroll
        for (int i = 0; i < 9; i++) {
            const float I = (i == 0 || i == 4 || i == 8) ? 1.0f : 0.0f;
            Re[i] = I + A * S[i] + B * S2[i];
            Vm[i] = I + B * S[i] + C * S2[i];
        }
        const float pe0 = Vm[0] * rho0 + Vm[1] * rho1 + Vm[2] * rho2;
        const float pe1 = Vm[3] * rho0 + Vm[4] * rho1 + Vm[5] * rho2;
        const float pe2 = Vm[6] * rho0 + Vm[7] * rho1 + Vm[8] * rho2;

        float Rn[9];
        #pragma unroll
        for (int i = 0; i < 3; i++)
            #pragma unroll
            for (int j = 0; j < 3; j++)
                Rn[i * 3 + j] = R[i * 3 + 0] * Re[0 + j] + R[i * 3 + 1] * Re[3 + j] + R[i * 3 + 2] * Re[6 + j];

        const float pn0 = R[0] * pe0 + R[1] * pe1 + R[2] * pe2 + p0;
        const float pn1 = R[3] * pe0 + R[4] * pe1 + R[5] * pe2 + p1;
        const float pn2 = R[6] * pe0 + R[7] * pe1 + R[8] * pe2 + p2;

        // Rinv = Rn^T, pinv = -Rinv @ pn
        float Ri[9] = {Rn[0], Rn[3], Rn[6], Rn[1], Rn[4], Rn[7], Rn[2], Rn[5], Rn[8]};
        const float pi0 = -(Ri[0] * pn0 + Ri[1] * pn1 + Ri[2] * pn2);
        const float pi1 = -(Ri[3] * pn0 + Ri[4] * pn1 + Ri[5] * pn2);
        const float pi2 = -(Ri[6] * pn0 + Ri[7] * pn1 + Ri[8] * pn2);

        // vI = Ad(R, p) @ v : top = R v[:3] + p x (R v[3:]), bot = R v[3:]
        const float u0 = R[0] * v[0] + R[1] * v[1] + R[2] * v[2];
        const float u1 = R[3] * v[0] + R[4] * v[1] + R[5] * v[2];
        const float u2 = R[6] * v[0] + R[7] * v[1] + R[8] * v[2];
        const float w0 = R[0] * v[3] + R[1] * v[4] + R[2] * v[5];
        const float w1 = R[3] * v[3] + R[4] * v[4] + R[5] * v[5];
        const float w2 = R[6] * v[3] + R[7] * v[4] + R[8] * v[5];
        const float t0 = u0 + (p1 * w2 - p2 * w1);
        const float t1 = u1 + (p2 * w0 - p0 * w2);
        const float t2 = u2 + (p0 * w1 - p1 * w0);

        float* se = sSE + r * 18;
        #pragma unroll
        for (int i = 0; i < 9; i++) se[i] = Ri[i];
        se[9]  = pi0; se[10] = pi1; se[11] = pi2;
        se[12] = t0;  se[13] = t1;  se[14] = t2;
        se[15] = w0;  se[16] = w1;  se[17] = w2;

        float* o = out + g * 18;
        o[0] = pn0; o[1] = pn1; o[2] = pn2;
        #pragma unroll
        for (int i = 0; i < 9; i++) o[3 + i] = Rn[i];
    }
    __syncthreads();

    // ---- phase 2: z1 = lrelu(h1 @ W1^T), [128 rows][128 cols] ----
    {
        const int c = tid & 127;
        float w[12];
        #pragma unroll
        for (int j = 0; j < 12; j++) w[j] = sW1[c * 12 + j];
        for (int r = tid >> 7; r < RPB; r += 2) {
            const float* h = sH1 + r * 12;
            float acc = 0.0f;
            #pragma unroll
            for (int j = 0; j < 12; j++) acc += h[j] * w[j];
            sZ1[r * WSTRIDE + c] = lrelu(acc);
        }
    }
    __syncthreads();

    // ---- phase 3: z2 = lrelu(z1 @ W2^T) (register-tiled 8x8) + dv = z2 @ W3^T ----
    {
        const int warp = tid >> 5;
        const int lane = tid & 31;
        const int half = lane >> 4;
        const int li   = lane & 15;
        const int r0   = warp * 16 + half * 8;   // 8 rows per thread
        // cols c_j = li + 16*j, j<8

        float acc[8][8];
        #pragma unroll
        for (int i = 0; i < 8; i++)
            #pragma unroll
            for (int j = 0; j < 8; j++) acc[i][j] = 0.0f;

        #pragma unroll 4
        for (int k = 0; k < 128; k += 4) {
            float4 rv[8], cv[8];
            #pragma unroll
            for (int i = 0; i < 8; i++)
                rv[i] = *(const float4*)(sZ1 + (r0 + i) * WSTRIDE + k);
            #pragma unroll
            for (int j = 0; j < 8; j++)
                cv[j] = *(const float4*)(sW2 + (li + 16 * j) * WSTRIDE + k);
            #pragma unroll
            for (int i = 0; i < 8; i++)
                #pragma unroll
                for (int j = 0; j < 8; j++) {
                    acc[i][j] += rv[i].x * cv[j].x;
                    acc[i][j] += rv[i].y * cv[j].y;
                    acc[i][j] += rv[i].z * cv[j].z;
                    acc[i][j] += rv[i].w * cv[j].w;
                }
        }

        #pragma unroll
        for (int i = 0; i < 8; i++)
            #pragma unroll
            for (int j = 0; j < 8; j++) acc[i][j] = lrelu(acc[i][j]);

        // dv partials over this thread's 8 cols
        float pd[8][6];
        #pragma unroll
        for (int i = 0; i < 8; i++)
            #pragma unroll
            for (int d = 0; d < 6; d++) pd[i][d] = 0.0f;

        #pragma unroll
        for (int j = 0; j < 8; j++) {
            const int c = li + 16 * j;
            #pragma unroll
            for (int d = 0; d < 6; d++) {
                const float w3 = sW3[d * 128 + c];
                #pragma unroll
                for (int i = 0; i < 8; i++) pd[i][d] += acc[i][j] * w3;
            }
        }

        // reduce across the 16 lanes that share rows (xor within half-warp)
        #pragma unroll
        for (int m = 1; m < 16; m <<= 1)
            #pragma unroll
            for (int i = 0; i < 8; i++)
                #pragma unroll
                for (int d = 0; d < 6; d++)
                    pd[i][d] += __shfl_xor_sync(0xffffffffu, pd[i][d], m);

        if (li == 0) {
            #pragma unroll
            for (int i = 0; i < 8; i++) {
                const int r = r0 + i;
                const long long g = rowBase + r;
                #pragma unroll
                for (int d = 0; d < 6; d++) {
                    sDV[r * 6 + d] = pd[i][d];
                    out[Kll * 30 + g * 6 + d] = pd[i][d];   // dv output
                }
            }
        }
    }
    __syncthreads();

    // ---- phase 4: v_next = Ad(Rinv, pinv) @ (vI + dv) ----
    if (tid < RPB) {
        const int r = tid;
        const long long g = rowBase + r;
        const float* se  = sSE + r * 18;
        const float* dvp = sDV + r * 6;

        float w6[6];
        #pragma unroll
        for (int i = 0; i < 6; i++) w6[i] = se[12 + i] + dvp[i];

        const float* Ri = se;
        const float pi0 = se[9], pi1 = se[10], pi2 = se[11];

        const float a0 = Ri[0] * w6[0] + Ri[1] * w6[1] + Ri[2] * w6[2];
        const float a1 = Ri[3] * w6[0] + Ri[4] * w6[1] + Ri[5] * w6[2];
        const float a2 = Ri[6] * w6[0] + Ri[7] * w6[1] + Ri[8] * w6[2];
        const float b0 = Ri[0] * w6[3] + Ri[1] * w6[4] + Ri[2] * w6[5];
        const float b1 = Ri[3] * w6[3] + Ri[4] * w6[4] + Ri[5] * w6[5];
        const float b2 = Ri[6] * w6[3] + Ri[7] * w6[4] + Ri[8] * w6[5];

        float* o = out + g * 18;
        o[12] = a0 + (pi1 * b2 - pi2 * b1);
        o[13] = a1 + (pi2 * b0 - pi0 * b2);
        o[14] = a2 + (pi0 * b1 - pi1 * b0);
        o[15] = b0;
        o[16] = b1;
        o[17] = b2;
    }
}

extern "C" void kernel_launch(void* const* d_in, const int* in_sizes, int n_in,
                              void* d_out, int out_size)
{
    const float* s   = (const float*)d_in[0];
    const float* a   = (const float*)d_in[1];
    const float* h0  = (const float*)d_in[2];
    const float* Wih = (const float*)d_in[3];
    const float* Whh = (const float*)d_in[4];
    const float* W1  = (const float*)d_in[5];
    const float* W2  = (const float*)d_in[6];
    const float* W3  = (const float*)d_in[7];
    float* out = (float*)d_out;

    const int Krows = in_sizes[0] / 18;      // s is [K,1,18]
    const int nblk = Krows / RPB;

    cudaFuncSetAttribute(auv_step_kernel,
                         cudaFuncAttributeMaxDynamicSharedMemorySize, SMEM_BYTES);
    auv_step_kernel<<<nblk, TPB, SMEM_BYTES>>>(s, a, h0, Wih, Whh, W1, W2, W3, out, Krows);
}

// round 2
// speedup vs baseline: 1.3496x; 1.3496x over previous
#include <cuda_runtime.h>
#include <math.h>

#define RPB 128      // rows per block
#define TPB 512      // threads per block (16 warps)
#define WSTRIDE 132  // padded row stride (floats): 528B, 16B-aligned, 4-bank step

// Shared layout (floats), all offsets 16B aligned:
#define OFF_W2   0                         // [128][132] = 16896
#define OFF_Z1   (OFF_W2  + 128*WSTRIDE)   // [128][132] = 16896
#define OFF_W1   (OFF_Z1  + 128*WSTRIDE)   // [128][12]  = 1536
#define OFF_W3   (OFF_W1  + 1536)          // [6][128]   = 768
#define OFF_WIH  (OFF_W3  + 768)           // [12][21]   = 252 pad 256
#define OFF_WHH  (OFF_WIH + 256)           // [12][12]   = 144
#define OFF_H1   (OFF_WHH + 144)           // [128][12]  = 1536
#define OFF_SE   (OFF_H1  + 1536)          // [128][18]  = 2304
#define OFF_DV   (OFF_SE  + 2304)          // [128][6]   = 768
#define OFF_S    (OFF_DV  + 768)           // [128][18]  = 2304
#define OFF_A    (OFF_S   + 2304)          // [128][6]   = 768
#define OFF_H0   (OFF_A   + 768)           // [128][12]  = 1536
#define SMEM_FLOATS (OFF_H0 + 1536)
#define SMEM_BYTES  (SMEM_FLOATS * 4)

__device__ __forceinline__ float lrelu(float z) { return z >= 0.0f ? z : 0.1f * z; }

// packed dual-fp32 FMA (Blackwell): d = a*b+c per 32-bit lane of the 64-bit regs
__device__ __forceinline__ unsigned long long ffma2(unsigned long long a,
                                                    unsigned long long b,
                                                    unsigned long long c) {
    unsigned long long d;
    asm("fma.rn.f32x2 %0, %1, %2, %3;" : "=l"(d) : "l"(a), "l"(b), "l"(c));
    return d;
}

__device__ __forceinline__ float unpack_sum(unsigned long long u) {
    float2 f;
    asm("mov.b64 {%0, %1}, %2;" : "=f"(f.x), "=f"(f.y) : "l"(u));
    return f.x + f.y;
}

__global__ __launch_bounds__(TPB, 1)
void auv_step_kernel(const float* __restrict__ s,
                     const float* __restrict__ a,
                     const float* __restrict__ h0,
                     const float* __restrict__ Wih,
                     const float* __restrict__ Whh,
                     const float* __restrict__ W1,
                     const float* __restrict__ W2,
                     const float* __restrict__ W3,
                     float* __restrict__ out,
                     int Krows)
{
    extern __shared__ float sm[];
    float* sW2  = sm + OFF_W2;
    float* sZ1  = sm + OFF_Z1;
    float* sW1  = sm + OFF_W1;
    float* sW3  = sm + OFF_W3;
    float* sWih = sm + OFF_WIH;
    float* sWhh = sm + OFF_WHH;
    float* sH1  = sm + OFF_H1;
    float* sSE  = sm + OFF_SE;
    float* sDV  = sm + OFF_DV;
    float* sS   = sm + OFF_S;
    float* sA   = sm + OFF_A;
    float* sH0  = sm + OFF_H0;

    const int tid = threadIdx.x;
    const long long rowBase = (long long)blockIdx.x * RPB;
    const long long Kll = (long long)Krows;

    // ---- cooperative staging (vectorized) ----
    {
        const float4* W2v = (const float4*)W2;
        #pragma unroll
        for (int i = tid; i < 4096; i += TPB) {           // 128x128 = 4096 float4
            float4 v = W2v[i];
            const int row = i >> 5, c4 = i & 31;
            *(float4*)(sW2 + row * WSTRIDE + c4 * 4) = v;
        }
        for (int i = tid; i < 384; i += TPB) ((float4*)sW1)[i] = ((const float4*)W1)[i];
        for (int i = tid; i < 192; i += TPB) ((float4*)sW3)[i] = ((const float4*)W3)[i];
        if (tid < 63)  ((float4*)sWih)[tid] = ((const float4*)Wih)[tid];   // 252 floats
        if (tid < 36)  ((float4*)sWhh)[tid] = ((const float4*)Whh)[tid];   // 144 floats
        const float4* sv = (const float4*)(s  + rowBase * 18);
        const float4* av = (const float4*)(a  + rowBase * 6);
        const float4* hv = (const float4*)(h0 + rowBase * 12);
        for (int i = tid; i < 576; i += TPB) ((float4*)sS)[i]  = sv[i];
        for (int i = tid; i < 192; i += TPB) ((float4*)sA)[i]  = av[i];
        for (int i = tid; i < 384; i += TPB) ((float4*)sH0)[i] = hv[i];
    }
    __syncthreads();

    // ---- phase 1: RNN cell (h1) + SE(3) per-row precompute (128 threads) ----
    if (tid < RPB) {
        const int r = tid;
        const float* Sr  = sS  + r * 18;
        const float* Ar  = sA  + r * 6;
        const float* H0r = sH0 + r * 12;

        float x[21];
        #pragma unroll
        for (int i = 0; i < 15; i++) x[i] = Sr[3 + i];
        #pragma unroll
        for (int i = 0; i < 6; i++) x[15 + i] = Ar[i];

        #pragma unroll
        for (int j = 0; j < 12; j++) {
            float acc = 0.0f;
            #pragma unroll
            for (int i = 0; i < 21; i++) acc += x[i] * sWih[j * 21 + i];
            #pragma unroll
            for (int i = 0; i < 12; i++) acc += H0r[i] * sWhh[j * 12 + i];
            sH1[r * 12 + j] = tanhf(acc);
        }

        // SE(3)
        const float p0 = Sr[0], p1 = Sr[1], p2 = Sr[2];
        float R[9];
        #pragma unroll
        for (int i = 0; i < 9; i++) R[i] = Sr[3 + i];
        float v[6];
        #pragma unroll
        for (int i = 0; i < 6; i++) v[i] = Sr[12 + i];

        const float DT = 0.1f;
        const float rho0 = v[0] * DT, rho1 = v[1] * DT, rho2 = v[2] * DT;
        const float px = v[3] * DT, py = v[4] * DT, pz = v[5] * DT;
        const float th2 = px * px + py * py + pz * pz;
        const bool small = th2 < 1e-8f;
        const float th2s = small ? 1.0f : th2;
        const float th = sqrtf(th2s);
        const float sth = sinf(th), cth = cosf(th);
        const float A = small ? (1.0f - th2 * (1.0f / 6.0f))  : (sth / th);
        const float B = small ? (0.5f - th2 * (1.0f / 24.0f)) : ((1.0f - cth) / th2s);
        const float C = small ? (1.0f / 6.0f - th2 * (1.0f / 120.0f)) : ((th - sth) / (th2s * th));

        const float S[9]  = {0.0f, -pz, py,  pz, 0.0f, -px,  -py, px, 0.0f};
        float S2[9];
        S2[0] = -(py * py + pz * pz); S2[1] = px * py;              S2[2] = px * pz;
        S2[3] = px * py;              S2[4] = -(px * px + pz * pz); S2[5] = py * pz;
        S2[6] = px * pz;              S2[7] = py * pz;              S2[8] = -(px * px + py * py);

        float Re[9], Vm[9];
        #pragma unroll
        for (int i = 0; i < 9; i++) {
            const float I = (i == 0 || i == 4 || i == 8) ? 1.0f : 0.0f;
            Re[i] = I + A * S[i] + B * S2[i];
            Vm[i] = I + B * S[i] + C * S2[i];
        }
        const float pe0 = Vm[0] * rho0 + Vm[1] * rho1 + Vm[2] * rho2;
        const float pe1 = Vm[3] * rho0 + Vm[4] * rho1 + Vm[5] * rho2;
        const float pe2 = Vm[6] * rho0 + Vm[7] * rho1 + Vm[8] * rho2;

        float Rn[9];
        #pragma unroll
        for (int i = 0; i < 3; i++)
            #pragma unroll
            for (int j = 0; j < 3; j++)
                Rn[i * 3 + j] = R[i * 3 + 0] * Re[0 + j] + R[i * 3 + 1] * Re[3 + j] + R[i * 3 + 2] * Re[6 + j];

        const float pn0 = R[0] * pe0 + R[1] * pe1 + R[2] * pe2 + p0;
        const float pn1 = R[3] * pe0 + R[4] * pe1 + R[5] * pe2 + p1;
        const float pn2 = R[6] * pe0 + R[7] * pe1 + R[8] * pe2 + p2;

        float Ri[9] = {Rn[0], Rn[3], Rn[6], Rn[1], Rn[4], Rn[7], Rn[2], Rn[5], Rn[8]};
        const float pi0 = -(Ri[0] * pn0 + Ri[1] * pn1 + Ri[2] * pn2);
        const float pi1 = -(Ri[3] * pn0 + Ri[4] * pn1 + Ri[5] * pn2);
        const float pi2 = -(Ri[6] * pn0 + Ri[7] * pn1 + Ri[8] * pn2);

        // vI = Ad(R, p) @ v
        const float u0 = R[0] * v[0] + R[1] * v[1] + R[2] * v[2];
        const float u1 = R[3] * v[0] + R[4] * v[1] + R[5] * v[2];
        const float u2 = R[6] * v[0] + R[7] * v[1] + R[8] * v[2];
        const float w0 = R[0] * v[3] + R[1] * v[4] + R[2] * v[5];
        const float w1 = R[3] * v[3] + R[4] * v[4] + R[5] * v[5];
        const float w2 = R[6] * v[3] + R[7] * v[4] + R[8] * v[5];
        const float t0 = u0 + (p1 * w2 - p2 * w1);
        const float t1 = u1 + (p2 * w0 - p0 * w2);
        const float t2 = u2 + (p0 * w1 - p1 * w0);

        float* se = sSE + r * 18;
        #pragma unroll
        for (int i = 0; i < 9; i++) se[i] = Ri[i];
        se[9]  = pi0; se[10] = pi1; se[11] = pi2;
        se[12] = t0;  se[13] = t1;  se[14] = t2;
        se[15] = w0;  se[16] = w1;  se[17] = w2;

        // s_next first 12 entries -> overwrite our own sS row (fully read already)
        float* o = sS + r * 18;
        o[0] = pn0; o[1] = pn1; o[2] = pn2;
        #pragma unroll
        for (int i = 0; i < 9; i++) o[3 + i] = Rn[i];
    }
    __syncthreads();

    // ---- phase 2: z1 = lrelu(h1 @ W1^T)  (packed over the 12-dim) ----
    {
        const int c = tid & 127;
        const unsigned long long* wp = (const unsigned long long*)(sW1 + c * 12); // 48B-aligned
        unsigned long long w[6];
        #pragma unroll
        for (int j = 0; j < 6; j++) w[j] = wp[j];
        for (int r = tid >> 7; r < RPB; r += 4) {
            const unsigned long long* hp = (const unsigned long long*)(sH1 + r * 12);
            unsigned long long acc = 0ull;
            #pragma unroll
            for (int j = 0; j < 6; j++) acc = ffma2(hp[j], w[j], acc);
            sZ1[r * WSTRIDE + c] = lrelu(unpack_sum(acc));
        }
    }
    __syncthreads();

    // ---- phase 3: z2 = lrelu(z1 @ W2^T) packed-over-K f32x2, then dv = z2 @ W3^T ----
    {
        const int warp = tid >> 5;
        const int lane = tid & 31;
        const int r0   = warp * 8;                 // 8 rows per warp
        // cols c_j = lane + 32*j, j<4

        unsigned long long acc2[8][4];
        #pragma unroll
        for (int i = 0; i < 8; i++)
            #pragma unroll
            for (int j = 0; j < 4; j++) acc2[i][j] = 0ull;

        #pragma unroll 2
        for (int k = 0; k < 128; k += 4) {
            ulonglong2 rv[8], cv[4];
            #pragma unroll
            for (int i = 0; i < 8; i++)
                rv[i] = *(const ulonglong2*)(sZ1 + (r0 + i) * WSTRIDE + k);   // warp-broadcast
            #pragma unroll
            for (int j = 0; j < 4; j++)
                cv[j] = *(const ulonglong2*)(sW2 + (lane + 32 * j) * WSTRIDE + k);
            #pragma unroll
            for (int i = 0; i < 8; i++)
                #pragma unroll
                for (int j = 0; j < 4; j++) {
                    acc2[i][j] = ffma2(rv[i].x, cv[j].x, acc2[i][j]);
                    acc2[i][j] = ffma2(rv[i].y, cv[j].y, acc2[i][j]);
                }
        }

        float z2[8][4];
        #pragma unroll
        for (int i = 0; i < 8; i++)
            #pragma unroll
            for (int j = 0; j < 4; j++) z2[i][j] = lrelu(unpack_sum(acc2[i][j]));

        // dv partials over this thread's 4 cols
        float pd[8][6];
        #pragma unroll
        for (int i = 0; i < 8; i++)
            #pragma unroll
            for (int d = 0; d < 6; d++) pd[i][d] = 0.0f;

        #pragma unroll
        for (int j = 0; j < 4; j++) {
            const int c = lane + 32 * j;
            #pragma unroll
            for (int d = 0; d < 6; d++) {
                const float w3 = sW3[d * 128 + c];
                #pragma unroll
                for (int i = 0; i < 8; i++) pd[i][d] += z2[i][j] * w3;
            }
        }

        // reduce across all 32 lanes
        #pragma unroll
        for (int m = 1; m < 32; m <<= 1)
            #pragma unroll
            for (int i = 0; i < 8; i++)
                #pragma unroll
                for (int d = 0; d < 6; d++)
                    pd[i][d] += __shfl_xor_sync(0xffffffffu, pd[i][d], m);

        if (lane == 0) {
            #pragma unroll
            for (int i = 0; i < 8; i++)
                #pragma unroll
                for (int d = 0; d < 6; d++) sDV[(r0 + i) * 6 + d] = pd[i][d];
        }
    }
    __syncthreads();

    // ---- phase 4: v_next = Ad(Rinv, pinv) @ (vI + dv) ----
    if (tid < RPB) {
        const int r = tid;
        const float* se  = sSE + r * 18;
        const float* dvp = sDV + r * 6;

        float w6[6];
        #pragma unroll
        for (int i = 0; i < 6; i++) w6[i] = se[12 + i] + dvp[i];

        const float* Ri = se;
        const float pi0 = se[9], pi1 = se[10], pi2 = se[11];

        const float a0 = Ri[0] * w6[0] + Ri[1] * w6[1] + Ri[2] * w6[2];
        const float a1 = Ri[3] * w6[0] + Ri[4] * w6[1] + Ri[5] * w6[2];
        const float a2 = Ri[6] * w6[0] + Ri[7] * w6[1] + Ri[8] * w6[2];
        const float b0 = Ri[0] * w6[3] + Ri[1] * w6[4] + Ri[2] * w6[5];
        const float b1 = Ri[3] * w6[3] + Ri[4] * w6[4] + Ri[5] * w6[5];
        const float b2 = Ri[6] * w6[3] + Ri[7] * w6[4] + Ri[8] * w6[5];

        float* o = sS + r * 18;
        o[12] = a0 + (pi1 * b2 - pi2 * b1);
        o[13] = a1 + (pi2 * b0 - pi0 * b2);
        o[14] = a2 + (pi0 * b1 - pi1 * b0);
        o[15] = b0;
        o[16] = b1;
        o[17] = b2;
    }
    __syncthreads();

    // ---- phase 5: coalesced vectorized dump of all three outputs ----
    {
        float4* d0 = (float4*)(out + rowBase * 18);               // s_next: 2304 floats
        float4* d1 = (float4*)(out + Kll * 18 + rowBase * 12);    // hN:     1536 floats
        float4* d2 = (float4*)(out + Kll * 30 + rowBase * 6);     // dv:      768 floats
        const float4* s0 = (const float4*)sS;
        const float4* s1 = (const float4*)sH1;
        const float4* s2 = (const float4*)sDV;
        for (int i = tid; i < 576; i += TPB) d0[i] = s0[i];
        for (int i = tid; i < 384; i += TPB) d1[i] = s1[i];
        for (int i = tid; i < 192; i += TPB) d2[i] = s2[i];
    }
}

extern "C" void kernel_launch(void* const* d_in, const int* in_sizes, int n_in,
                              void* d_out, int out_size)
{
    const float* s   = (const float*)d_in[0];
    const float* a   = (const float*)d_in[1];
    const float* h0  = (const float*)d_in[2];
    const float* Wih = (const float*)d_in[3];
    const float* Whh = (const float*)d_in[4];
    const float* W1  = (const float*)d_in[5];
    const float* W2  = (const float*)d_in[6];
    const float* W3  = (const float*)d_in[7];
    float* out = (float*)d_out;

    const int Krows = in_sizes[0] / 18;      // s is [K,1,18]
    const int nblk = Krows / RPB;

    cudaFuncSetAttribute(auv_step_kernel,
                         cudaFuncAttributeMaxDynamicSharedMemorySize, SMEM_BYTES);
    auv_step_kernel<<<nblk, TPB, SMEM_BYTES>>>(s, a, h0, Wih, Whh, W1, W2, W3, out, Krows);
}